// round 1
// baseline (speedup 1.0000x reference)
#include <cuda_runtime.h>
#include <cuda_bf16.h>

// ---------------------------------------------------------------------------
// Problem constants
// ---------------------------------------------------------------------------
constexpr int BATCH  = 128;
constexpr int NPTS   = 65536;
constexpr int NPT    = 10;     // NPOINT
constexpr int NS     = 8;      // NSAMPLE
constexpr int NPOS   = BATCH * NPT * NS;  // 10240 positions through the conv stack

constexpr int FPS_T  = 1024;
constexpr int PPT    = NPTS / FPS_T;      // 64 points per thread

// ---------------------------------------------------------------------------
// Device scratch (no allocations allowed)
// ---------------------------------------------------------------------------
__device__ float g_newxyz[BATCH * NPT * 3];          // FPS centroids
__device__ float g_grouped[NPOS * 3];                // relative coords [b][s][k][c]
__device__ float g_act1[NPOS * 8];                   // layer1 output (post BN+relu)
__device__ float g_act2[NPOS * 8];                   // layer2 output
__device__ float g_feat[BATCH * 160];                // maxpooled features
__device__ float g_h[BATCH * 128];                   // fc1 output (post BN+relu)

// ---------------------------------------------------------------------------
// Helpers: deterministic block reduction of (sum, sumsq) in double
// ---------------------------------------------------------------------------
template <int NWARP>
__device__ __forceinline__ void block_red2(double& s, double& s2, double* sm) {
    const unsigned full = 0xFFFFFFFFu;
    #pragma unroll
    for (int off = 16; off > 0; off >>= 1) {
        s  += __shfl_down_sync(full, s,  off);
        s2 += __shfl_down_sync(full, s2, off);
    }
    int w = threadIdx.x >> 5, l = threadIdx.x & 31;
    if (l == 0) { sm[w * 2] = s; sm[w * 2 + 1] = s2; }
    __syncthreads();
    if (threadIdx.x == 0) {
        double a = 0.0, b = 0.0;
        #pragma unroll
        for (int i = 0; i < NWARP; i++) { a += sm[i * 2]; b += sm[i * 2 + 1]; }
        sm[0] = a; sm[1] = b;
    }
    __syncthreads();
    s = sm[0]; s2 = sm[1];
}

// ---------------------------------------------------------------------------
// Kernel 1: Farthest point sampling. One CTA per batch.
// dist[] kept per-thread (local, L1-backed). Exact unfused arithmetic to
// match the reference's distance values bit-for-bit; first-index tie-break.
// ---------------------------------------------------------------------------
__global__ void __launch_bounds__(FPS_T, 1) fps_kernel(const float* __restrict__ pc) {
    const int b = blockIdx.x;
    const int t = threadIdx.x;
    const float* __restrict__ px = pc + (size_t)b * 3 * NPTS;
    const float* __restrict__ py = px + NPTS;
    const float* __restrict__ pz = px + 2 * NPTS;

    __shared__ float s_c[3];
    __shared__ float s_val[FPS_T];
    __shared__ int   s_idx[FPS_T];

    float dist[PPT];
    #pragma unroll
    for (int i = 0; i < PPT; i++) dist[i] = 1e10f;

    if (t == 0) {
        float cx = px[0], cy = py[0], cz = pz[0];
        s_c[0] = cx; s_c[1] = cy; s_c[2] = cz;
        float* o = &g_newxyz[b * NPT * 3];
        o[0] = cx; o[1] = cy; o[2] = cz;
    }
    __syncthreads();

    const int base = t * PPT;
    for (int it = 1; it < NPT; ++it) {
        const float cx = s_c[0], cy = s_c[1], cz = s_c[2];
        float bv = -1e30f;
        int   bi = 0;
        #pragma unroll 8
        for (int i = 0; i < PPT; i++) {
            int n = base + i;
            float dx = __fadd_rn(px[n], -cx);
            float dy = __fadd_rn(py[n], -cy);
            float dz = __fadd_rn(pz[n], -cz);
            float d  = __fadd_rn(__fadd_rn(__fmul_rn(dx, dx), __fmul_rn(dy, dy)),
                                 __fmul_rn(dz, dz));
            float dd = fminf(dist[i], d);
            dist[i] = dd;
            if (dd > bv) { bv = dd; bi = n; }   // ascending scan → first max kept
        }
        s_val[t] = bv; s_idx[t] = bi;
        __syncthreads();
        for (int off = FPS_T / 2; off > 0; off >>= 1) {
            if (t < off) {
                float v2 = s_val[t + off];
                int   i2 = s_idx[t + off];
                if (v2 > s_val[t] || (v2 == s_val[t] && i2 < s_idx[t])) {
                    s_val[t] = v2; s_idx[t] = i2;
                }
            }
            __syncthreads();
        }
        if (t == 0) {
            int fi = s_idx[0];
            float cx2 = px[fi], cy2 = py[fi], cz2 = pz[fi];
            s_c[0] = cx2; s_c[1] = cy2; s_c[2] = cz2;
            float* o = &g_newxyz[(b * NPT + it) * 3];
            o[0] = cx2; o[1] = cy2; o[2] = cz2;
        }
        __syncthreads();
    }
}

// ---------------------------------------------------------------------------
// Kernel 2: ball query + grouping. One warp per (batch, centroid).
// Reference uses sq = |c|^2 + |p|^2 - 2 c.p, keeps sq <= r^2, takes the 8
// LOWEST point indices, pads with the first. Early exit once 8 found.
// ---------------------------------------------------------------------------
__global__ void ballquery_kernel(const float* __restrict__ pc) {
    int wid  = (blockIdx.x * blockDim.x + threadIdx.x) >> 5;
    int lane = threadIdx.x & 31;
    if (wid >= BATCH * NPT) return;
    int b = wid / NPT;

    const float* __restrict__ px = pc + (size_t)b * 3 * NPTS;
    const float* __restrict__ py = px + NPTS;
    const float* __restrict__ pz = px + 2 * NPTS;
    const float* c = &g_newxyz[wid * 3];
    const float cx = c[0], cy = c[1], cz = c[2];
    const float cn2 = __fadd_rn(__fadd_rn(__fmul_rn(cx, cx), __fmul_rn(cy, cy)),
                                __fmul_rn(cz, cz));
    const float R2 = 0.04f;  // float(0.2**2)

    int found = 0;
    int idxs[NS];
    for (int base = 0; base < NPTS && found < NS; base += 32) {
        int n = base + lane;
        float x = px[n], y = py[n], z = pz[n];
        float pn2 = __fadd_rn(__fadd_rn(__fmul_rn(x, x), __fmul_rn(y, y)),
                              __fmul_rn(z, z));
        float dot = __fadd_rn(__fadd_rn(__fmul_rn(cx, x), __fmul_rn(cy, y)),
                              __fmul_rn(cz, z));
        float sq  = __fadd_rn(__fadd_rn(cn2, pn2), -__fmul_rn(2.0f, dot));
        unsigned m = __ballot_sync(0xFFFFFFFFu, sq <= R2);
        while (m && found < NS) {
            int l = __ffs(m) - 1;
            m &= m - 1;
            idxs[found++] = base + l;
        }
    }
    // pad with first found (centroid itself is always in-ball: sq == 0 exactly)
    for (int k = found; k < NS; k++) idxs[k] = idxs[0];

    if (lane < NS) {
        int n = idxs[lane];
        float* o = &g_grouped[(wid * NS + lane) * 3];
        o[0] = __fadd_rn(px[n], -cx);
        o[1] = __fadd_rn(py[n], -cy);
        o[2] = __fadd_rn(pz[n], -cz);
    }
}

// ---------------------------------------------------------------------------
// Conv layers: one CTA per output channel; CTA sees ALL 10240 positions →
// in-block deterministic BN statistics, single pass per layer.
// ---------------------------------------------------------------------------
__global__ void __launch_bounds__(1024) layer1_kernel(
    const float* __restrict__ w, const float* __restrict__ bias,
    const float* __restrict__ g, const float* __restrict__ be) {
    const int c = blockIdx.x, t = threadIdx.x;
    const float w0 = w[c * 3], w1 = w[c * 3 + 1], w2 = w[c * 3 + 2], bb = bias[c];
    float z[10];
    double s = 0.0, s2 = 0.0;
    #pragma unroll
    for (int i = 0; i < 10; i++) {
        int pos = t + i * 1024;
        const float* x = &g_grouped[pos * 3];
        float zz = w0 * x[0] + w1 * x[1] + w2 * x[2] + bb;
        z[i] = zz; s += zz; s2 += (double)zz * zz;
    }
    __shared__ double red[64];
    block_red2<32>(s, s2, red);
    __shared__ float s_sc, s_sh;
    if (t == 0) {
        double mean = s / NPOS;
        double var  = s2 / NPOS - mean * mean;
        float inv = rsqrtf((float)var + 1e-5f) * g[c];
        s_sc = inv; s_sh = be[c] - (float)mean * inv;
    }
    __syncthreads();
    const float sc = s_sc, sh = s_sh;
    #pragma unroll
    for (int i = 0; i < 10; i++) {
        int pos = t + i * 1024;
        g_act1[pos * 8 + c] = fmaxf(z[i] * sc + sh, 0.0f);
    }
}

__global__ void __launch_bounds__(1024) layer2_kernel(
    const float* __restrict__ w, const float* __restrict__ bias,
    const float* __restrict__ g, const float* __restrict__ be) {
    const int c = blockIdx.x, t = threadIdx.x;
    float wr[8];
    #pragma unroll
    for (int j = 0; j < 8; j++) wr[j] = w[c * 8 + j];
    const float bb = bias[c];
    float z[10];
    double s = 0.0, s2 = 0.0;
    #pragma unroll
    for (int i = 0; i < 10; i++) {
        int pos = t + i * 1024;
        const float* a = &g_act1[pos * 8];
        float zz = bb;
        #pragma unroll
        for (int j = 0; j < 8; j++) zz += wr[j] * a[j];
        z[i] = zz; s += zz; s2 += (double)zz * zz;
    }
    __shared__ double red[64];
    block_red2<32>(s, s2, red);
    __shared__ float s_sc, s_sh;
    if (t == 0) {
        double mean = s / NPOS;
        double var  = s2 / NPOS - mean * mean;
        float inv = rsqrtf((float)var + 1e-5f) * g[c];
        s_sc = inv; s_sh = be[c] - (float)mean * inv;
    }
    __syncthreads();
    const float sc = s_sc, sh = s_sh;
    #pragma unroll
    for (int i = 0; i < 10; i++) {
        int pos = t + i * 1024;
        g_act2[pos * 8 + c] = fmaxf(z[i] * sc + sh, 0.0f);
    }
}

// layer3 (8→16) fused with maxpool over nsample. One CTA per out channel (16).
__global__ void __launch_bounds__(1024) layer3_kernel(
    const float* __restrict__ w, const float* __restrict__ bias,
    const float* __restrict__ g, const float* __restrict__ be) {
    const int c = blockIdx.x, t = threadIdx.x;
    float wr[8];
    #pragma unroll
    for (int j = 0; j < 8; j++) wr[j] = w[c * 8 + j];
    const float bb = bias[c];
    float z[10];
    double s = 0.0, s2 = 0.0;
    #pragma unroll
    for (int i = 0; i < 10; i++) {
        int pos = t + i * 1024;
        const float* a = &g_act2[pos * 8];
        float zz = bb;
        #pragma unroll
        for (int j = 0; j < 8; j++) zz += wr[j] * a[j];
        z[i] = zz; s += zz; s2 += (double)zz * zz;
    }
    __shared__ double red[64];
    block_red2<32>(s, s2, red);
    __shared__ float s_sc, s_sh;
    if (t == 0) {
        double mean = s / NPOS;
        double var  = s2 / NPOS - mean * mean;
        float inv = rsqrtf((float)var + 1e-5f) * g[c];
        s_sc = inv; s_sh = be[c] - (float)mean * inv;
    }
    __syncthreads();
    const float sc = s_sc, sh = s_sh;
    __shared__ float sa[NPOS];  // 40 KB
    #pragma unroll
    for (int i = 0; i < 10; i++) {
        int pos = t + i * 1024;
        sa[pos] = fmaxf(z[i] * sc + sh, 0.0f);
    }
    __syncthreads();
    // maxpool over the 8 samples per (b, s) group; feat layout [b][c*10 + s]
    for (int gidx = t; gidx < BATCH * NPT; gidx += 1024) {
        float m = sa[gidx * 8];
        #pragma unroll
        for (int k = 1; k < 8; k++) m = fmaxf(m, sa[gidx * 8 + k]);
        int b = gidx / NPT, ss = gidx % NPT;
        g_feat[b * 160 + c * 10 + ss] = m;
    }
}

// fc1 (160→128) fused with per-feature batch-norm over B=128 + relu.
// One CTA per output feature; threads = batch index → full BN stats in-block.
__global__ void __launch_bounds__(128) fc1_kernel(
    const float* __restrict__ w, const float* __restrict__ bias,
    const float* __restrict__ g, const float* __restrict__ be) {
    const int o = blockIdx.x, b = threadIdx.x;
    const float* wr = &w[o * 160];
    const float* f  = &g_feat[b * 160];
    float acc = 0.0f;
    #pragma unroll
    for (int i = 0; i < 160; i++) acc += wr[i] * f[i];
    const float h = acc + bias[o];

    double s = h, s2 = (double)h * h;
    __shared__ double red[8];
    block_red2<4>(s, s2, red);
    __shared__ float s_sc, s_sh;
    if (b == 0) {
        double mean = s / BATCH;
        double var  = s2 / BATCH - mean * mean;
        float inv = rsqrtf((float)var + 1e-5f) * g[o];
        s_sc = inv; s_sh = be[o] - (float)mean * inv;
    }
    __syncthreads();
    g_h[b * 128 + o] = fmaxf(h * s_sc + s_sh, 0.0f);
}

// fc2 (128→25), final output.
__global__ void fc2_kernel(const float* __restrict__ w, const float* __restrict__ bias,
                           float* __restrict__ out) {
    const int b = blockIdx.x, o = threadIdx.x;
    if (o < 25) {
        const float* h  = &g_h[b * 128];
        const float* wr = &w[o * 128];
        float acc = 0.0f;
        #pragma unroll
        for (int i = 0; i < 128; i++) acc += h[i] * wr[i];
        out[b * 25 + o] = acc + bias[o];
    }
}

// ---------------------------------------------------------------------------
// Launch
// ---------------------------------------------------------------------------
extern "C" void kernel_launch(void* const* d_in, const int* in_sizes, int n_in,
                              void* d_out, int out_size) {
    (void)in_sizes; (void)n_in; (void)out_size;
    const float* pc    = (const float*)d_in[0];
    const float* w1    = (const float*)d_in[1];
    const float* b1    = (const float*)d_in[2];
    const float* g1    = (const float*)d_in[3];
    const float* be1   = (const float*)d_in[4];
    const float* w2    = (const float*)d_in[5];
    const float* b2    = (const float*)d_in[6];
    const float* g2    = (const float*)d_in[7];
    const float* be2   = (const float*)d_in[8];
    const float* w3    = (const float*)d_in[9];
    const float* b3    = (const float*)d_in[10];
    const float* g3    = (const float*)d_in[11];
    const float* be3   = (const float*)d_in[12];
    const float* fc1w  = (const float*)d_in[13];
    const float* fc1b  = (const float*)d_in[14];
    const float* bn1g  = (const float*)d_in[15];
    const float* bn1b  = (const float*)d_in[16];
    const float* fc2w  = (const float*)d_in[17];
    const float* fc2b  = (const float*)d_in[18];
    float* out = (float*)d_out;

    fps_kernel<<<BATCH, FPS_T>>>(pc);
    ballquery_kernel<<<(BATCH * NPT * 32 + 255) / 256, 256>>>(pc);
    layer1_kernel<<<8, 1024>>>(w1, b1, g1, be1);
    layer2_kernel<<<8, 1024>>>(w2, b2, g2, be2);
    layer3_kernel<<<16, 1024>>>(w3, b3, g3, be3);
    fc1_kernel<<<128, 128>>>(fc1w, fc1b, bn1g, bn1b);
    fc2_kernel<<<128, 32>>>(fc2w, fc2b, out);
}